// round 1
// baseline (speedup 1.0000x reference)
#include <cuda_runtime.h>

#define SEQ   4096
#define CIN   7
#define NUMK  74
#define KH    8
#define KW    3
#define D     1536
#define HALFD 768
#define TLEN  (SEQ * KW)   // 12288

// ---------------- precomputed tables (device globals; no allocation) ----------------
// A[hi][i] = (sin(64*hi*div_i), cos(64*hi*div_i)),  B[lo][i] = (sin(lo*div_i), cos(lo*div_i))
__device__ float g_A[64][HALFD][2];
__device__ float g_B[64][HALFD][2];
// T2[a*7+b][f] = g(a)[f] + g(b)[f]   (temporal pair sums; indices are 0..6)
__device__ float g_T2[49][D];

__global__ void init_tables_kernel()
{
    int idx = blockIdx.x * blockDim.x + threadIdx.x;
    const float cexp = (float)(-9.210340371976184 / 1536.0); // -ln(10000)/d

    if (idx < 64 * HALFD) {
        int i = idx % HALFD;
        int r = idx / HALFD;
        float div = expf((2.0f * (float)i) * cexp);
        float sh, ch, sl, cl;
        sincosf((float)(64 * r) * div, &sh, &ch);
        g_A[r][i][0] = sh; g_A[r][i][1] = ch;
        sincosf((float)r * div, &sl, &cl);
        g_B[r][i][0] = sl; g_B[r][i][1] = cl;
    }
    if (idx < 49 * HALFD) {
        int i = idx % HALFD;
        int p = idx / HALFD;
        int a = p / 7, b = p % 7;
        float div = expf((2.0f * (float)i) * cexp);
        float sa, ca, sb, cb;
        sincosf((float)a * div, &sa, &ca);
        sincosf((float)b * div, &sb, &cb);
        g_T2[p][2 * i]     = sa + sb;
        g_T2[p][2 * i + 1] = ca + cb;
    }
}

// ---------------- main kernel: one block per s ----------------
__global__ __launch_bounds__(128) void embed_kernel(
    const float* __restrict__ x,       // (4096, 7)
    const float* __restrict__ kern,    // (74, 8, 3)
    const int*   __restrict__ xm,      // (4096, 4)
    float*       __restrict__ out)     // (4096, 1536)
{
    __shared__ float wcs[KH][76];      // [k][o], padded row
    __shared__ float sx[CIN][10];      // seq window for this s

    const int s   = blockIdx.x;
    const int tid = threadIdx.x;

    // Stage middle-column weights: wc[o][k] = kern[o*24 + k*3 + 1]
    for (int e = tid; e < NUMK * KH; e += 128) {
        int o = e / KH, k = e - o * KH;
        wcs[k][o] = kern[o * (KH * KW) + k * KW + 1];
    }
    // Stage x window: t in [3s-4, 3s+5], seqs[c][t] = x[min(t/3 + t%3, 4095)][c], 0 outside
    if (tid < CIN * 10) {
        int c = tid / 10, lt = tid - c * 10;
        int t = 3 * s - 4 + lt;
        float v = 0.0f;
        if (t >= 0 && t < TLEN) {
            int row = t / 3 + t % 3;
            if (row > SEQ - 1) row = SEQ - 1;
            v = x[row * CIN + c];
        }
        sx[c][lt] = v;
    }
    __syncthreads();

    const int g0 = 4 * tid;            // 0..508

    // per-lane (c, o)
    int cc[4], oo[4];
#pragma unroll
    for (int le = 0; le < 4; le++) {
        int gg = g0 + le;
        if (gg == 511) { cc[le] = 0; oo[le] = NUMK - 1; }
        else           { cc[le] = gg / 73; oo[le] = gg - cc[le] * 73; }
    }

    // weights into registers (reused for all 3 j)
    float wr[4][8];
#pragma unroll
    for (int le = 0; le < 4; le++)
#pragma unroll
        for (int k = 0; k < 8; k++)
            wr[le][k] = wcs[k][oo[le]];

    const bool uni = (cc[0] == cc[3]);   // gg==511 sets cc=0 != 6, so last thread is non-uni
    float sxr[10];
    if (uni) {
#pragma unroll
        for (int lt = 0; lt < 10; lt++) sxr[lt] = sx[cc[0]][lt];
    }

    // pe rows
    const int hi = s >> 6, lo = s & 63;
    const float* __restrict__ Arow = &g_A[hi][0][0];
    const float* __restrict__ Brow = &g_B[lo][0][0];
    // temporal rows
    const int i0 = xm[s * 4 + 0], i1 = xm[s * 4 + 1],
              i2 = xm[s * 4 + 2], i3 = xm[s * 4 + 3];
    const float* __restrict__ T2a = g_T2[i3 * 7 + i2];
    const float* __restrict__ T2b = g_T2[i1 * 7 + i0];

    float* __restrict__ outrow = out + (size_t)s * D;

#pragma unroll
    for (int j = 0; j < 3; j++) {
        const int f = j * 512 + g0;

        float acc[4];
        if (uni) {
#pragma unroll
            for (int le = 0; le < 4; le++) {
                float a = 0.0f;
#pragma unroll
                for (int k = 0; k < 8; k++) a += sxr[j + k] * wr[le][k];
                acc[le] = a;
            }
        } else {
#pragma unroll
            for (int le = 0; le < 4; le++) {
                float a = 0.0f;
#pragma unroll
                for (int k = 0; k < 8; k++) a += sx[cc[le]][j + k] * wr[le][k];
                acc[le] = a;
            }
        }

        // pe via angle addition: Arow+f = {sA_i, cA_i, sA_{i+1}, cA_{i+1}}
        const float4 av = *(const float4*)(Arow + f);
        const float4 bv = *(const float4*)(Brow + f);
        const float pe0 = av.x * bv.y + av.y * bv.x;   // sin
        const float pe1 = av.y * bv.y - av.x * bv.x;   // cos
        const float pe2 = av.z * bv.w + av.w * bv.z;
        const float pe3 = av.w * bv.w - av.z * bv.z;

        const float4 ta = *(const float4*)(T2a + f);
        const float4 tb = *(const float4*)(T2b + f);

        float4 r;
        r.x = acc[0] + pe0 + ta.x + tb.x;
        r.y = acc[1] + pe1 + ta.y + tb.y;
        r.z = acc[2] + pe2 + ta.z + tb.z;
        r.w = acc[3] + pe3 + ta.w + tb.w;
        *(float4*)(outrow + f) = r;
    }
}

// ---------------- launch ----------------
extern "C" void kernel_launch(void* const* d_in, const int* in_sizes, int n_in,
                              void* d_out, int out_size)
{
    const float* x    = nullptr;
    const float* kern = nullptr;
    const int*   xmark = nullptr;
    for (int i = 0; i < n_in; i++) {
        if      (in_sizes[i] == SEQ * CIN)        x     = (const float*)d_in[i];
        else if (in_sizes[i] == NUMK * KH * KW)   kern  = (const float*)d_in[i];
        else if (in_sizes[i] == SEQ * 4)          xmark = (const int*)d_in[i];
    }

    init_tables_kernel<<<(64 * HALFD + 255) / 256, 256>>>();
    embed_kernel<<<SEQ, 128>>>(x, kern, xmark, (float*)d_out);
}

// round 2
// speedup vs baseline: 1.4726x; 1.4726x over previous
#include <cuda_runtime.h>

#define SEQ   4096
#define CIN   7
#define NUMK  74
#define KH    8
#define KW    3
#define D     1536
#define HALFD 768
#define TLEN  (SEQ * KW)   // 12288
#define SPER  8            // s-rows per block

// ---------------- precomputed tables (device globals; no allocation) ----------------
// A[hi][i] = (sin(64*hi*div_i), cos(64*hi*div_i)),  B[lo][i] = (sin(lo*div_i), cos(lo*div_i))
__device__ float g_A[64][HALFD][2];
__device__ float g_B[64][HALFD][2];
// T2[a*7+b][f] = g(a)[f] + g(b)[f]   (temporal pair sums; indices are 0..6)
__device__ float g_T2[49][D];

__global__ void init_tables_kernel()
{
    int idx = blockIdx.x * blockDim.x + threadIdx.x;
    const float cexp = (float)(-9.210340371976184 / 1536.0); // -ln(10000)/d

    if (idx < 64 * HALFD) {
        int i = idx % HALFD;
        int r = idx / HALFD;
        float div = expf((2.0f * (float)i) * cexp);
        float sh, ch, sl, cl;
        sincosf((float)(64 * r) * div, &sh, &ch);
        g_A[r][i][0] = sh; g_A[r][i][1] = ch;
        sincosf((float)r * div, &sl, &cl);
        g_B[r][i][0] = sl; g_B[r][i][1] = cl;
    }
    if (idx < 49 * HALFD) {
        int i = idx % HALFD;
        int p = idx / HALFD;
        int a = p / 7, b = p % 7;
        float div = expf((2.0f * (float)i) * cexp);
        float sa, ca, sb, cb;
        sincosf((float)a * div, &sa, &ca);
        sincosf((float)b * div, &sb, &cb);
        g_T2[p][2 * i]     = sa + sb;
        g_T2[p][2 * i + 1] = ca + cb;
    }
}

// ---------------- main kernel: SPER s-rows per block ----------------
__global__ __launch_bounds__(128) void embed_kernel(
    const float* __restrict__ x,       // (4096, 7)
    const float* __restrict__ kern,    // (74, 8, 3)
    const int*   __restrict__ xm,      // (4096, 4)
    float*       __restrict__ out)     // (4096, 1536)
{
    __shared__ float wcs[KH][76];      // [k][o], padded row
    __shared__ float sx[CIN][36];      // window: 3*SPER+7 = 31 used, pad 36
    __shared__ int   t2i[SPER][2];     // temporal pair-table indices per row

    const int s0  = blockIdx.x * SPER;          // aligned: hi = s>>6 constant in block
    const int tid = threadIdx.x;

    // ---- stage weights: wc[o][k] = kern[o*24 + k*3 + 1]
    for (int e = tid; e < NUMK * KH; e += 128) {
        int o = e / KH, k = e - o * KH;
        wcs[k][o] = kern[o * (KH * KW) + k * KW + 1];
    }
    // ---- stage x window: i in [0,31), t = 3*s0 - 4 + i
    for (int e = tid; e < CIN * 31; e += 128) {
        int c = e / 31, i = e - c * 31;
        int t = 3 * s0 - 4 + i;
        float v = 0.0f;
        if (t >= 0 && t < TLEN) {
            int row = t / 3 + t % 3;
            if (row > SEQ - 1) row = SEQ - 1;
            v = x[row * CIN + c];
        }
        sx[c][i] = v;
    }
    // ---- stage temporal table indices
    if (tid < SPER) {
        int s = s0 + tid;
        int i0 = xm[s * 4 + 0], i1 = xm[s * 4 + 1],
            i2 = xm[s * 4 + 2], i3 = xm[s * 4 + 3];
        t2i[tid][0] = i3 * 7 + i2;
        t2i[tid][1] = i1 * 7 + i0;
    }
    __syncthreads();

    const int g0 = 4 * tid;            // 0..508

    // per-lane (c, o); a thread spans at most 2 distinct c (ca = cc of lane0, cb = cc of lane3)
    int cc[4], oo[4];
#pragma unroll
    for (int le = 0; le < 4; le++) {
        int gg = g0 + le;
        if (gg == 511) { cc[le] = 0; oo[le] = NUMK - 1; }
        else           { cc[le] = gg / 73; oo[le] = gg - cc[le] * 73; }
    }
    const int ca = cc[0], cb = cc[3];
    bool sel[4];
#pragma unroll
    for (int le = 0; le < 4; le++) sel[le] = (cc[le] == ca);

    // weights into registers (reused for all rows & j)
    float wr[4][8];
#pragma unroll
    for (int le = 0; le < 4; le++)
#pragma unroll
        for (int k = 0; k < 8; k++)
            wr[le][k] = wcs[k][oo[le]];

    // pe hi-part: constant across the block's 8 rows -> registers
    const int hi = s0 >> 6;
    const float* __restrict__ Abase = &g_A[hi][0][0];
    float4 av[3];
#pragma unroll
    for (int j = 0; j < 3; j++)
        av[j] = *(const float4*)(Abase + j * 512 + g0);

    // ---- per-row loop
#pragma unroll 2
    for (int r = 0; r < SPER; r++) {
        const int s = s0 + r;
        const float* __restrict__ Brow = &g_B[s & 63][0][0];
        const float* __restrict__ T2a  = g_T2[t2i[r][0]];
        const float* __restrict__ T2b  = g_T2[t2i[r][1]];
        float* __restrict__ outrow = out + (size_t)s * D;

        // register windows for the (<=2) channels this thread touches
        float sxa[10], sxb[10];
#pragma unroll
        for (int lt = 0; lt < 10; lt++) {
            sxa[lt] = sx[ca][3 * r + lt];
            sxb[lt] = sx[cb][3 * r + lt];
        }

#pragma unroll
        for (int j = 0; j < 3; j++) {
            const int f = j * 512 + g0;

            const float4 bv = *(const float4*)(Brow + f);
            const float4 ta = *(const float4*)(T2a + f);
            const float4 tb = *(const float4*)(T2b + f);

            float acc[4];
#pragma unroll
            for (int le = 0; le < 4; le++) {
                float a = 0.0f;
#pragma unroll
                for (int k = 0; k < 8; k++) {
                    float v = sel[le] ? sxa[j + k] : sxb[j + k];
                    a += v * wr[le][k];
                }
                acc[le] = a;
            }

            // pe via angle addition
            const float4 a4 = av[j];
            const float pe0 = a4.x * bv.y + a4.y * bv.x;   // sin
            const float pe1 = a4.y * bv.y - a4.x * bv.x;   // cos
            const float pe2 = a4.z * bv.w + a4.w * bv.z;
            const float pe3 = a4.w * bv.w - a4.z * bv.z;

            float4 rres;
            rres.x = acc[0] + pe0 + ta.x + tb.x;
            rres.y = acc[1] + pe1 + ta.y + tb.y;
            rres.z = acc[2] + pe2 + ta.z + tb.z;
            rres.w = acc[3] + pe3 + ta.w + tb.w;
            *(float4*)(outrow + f) = rres;
        }
    }
}

// ---------------- launch ----------------
extern "C" void kernel_launch(void* const* d_in, const int* in_sizes, int n_in,
                              void* d_out, int out_size)
{
    const float* x     = nullptr;
    const float* kern  = nullptr;
    const int*   xmark = nullptr;
    for (int i = 0; i < n_in; i++) {
        if      (in_sizes[i] == SEQ * CIN)        x     = (const float*)d_in[i];
        else if (in_sizes[i] == NUMK * KH * KW)   kern  = (const float*)d_in[i];
        else if (in_sizes[i] == SEQ * 4)          xmark = (const int*)d_in[i];
    }

    init_tables_kernel<<<(64 * HALFD + 255) / 256, 256>>>();
    embed_kernel<<<SEQ / SPER, 128>>>(x, kern, xmark, (float*)d_out);
}